// round 7
// baseline (speedup 1.0000x reference)
#include <cuda_runtime.h>
#include <cuda_fp16.h>

#define IN_C 128
#define MAX_NODES 10000
#define MAX_EDGES 640000

// Scratch (allocation-free rule: __device__ globals)
__device__ float  g_Wt[IN_C * IN_C];            // W transposed
__device__ __half g_xh[MAX_NODES * IN_C];       // fp16 copy of x for gather
__device__ int    g_cnt[MAX_NODES];             // edge-only in-degree
__device__ float  g_dinv[MAX_NODES];            // 1/sqrt(deg+1)
__device__ int    g_ptr[MAX_NODES + 1];         // CSR offsets (by destination)
__device__ int    g_cur[MAX_NODES];             // fill cursors
__device__ int    g_erow[MAX_EDGES];            // CSR source-node list

// ---------------------------------------------------------------------------
// Per-block edge-index dtype detection: int64 data has all-zero odd 32-bit
// words (ids < 2^31); int32 data essentially never does (64 random ids all 0).
// ---------------------------------------------------------------------------
__device__ __forceinline__ int block_is64(const int* __restrict__ ei32) {
    int pred = 0;
    if (threadIdx.x < 64) pred = (ei32[2 * threadIdx.x + 1] != 0);
    return __syncthreads_or(pred) ? 0 : 1;
}

// ---------------------------------------------------------------------------
// Fused prologue: zero cnt + transpose W + x -> fp16
// ---------------------------------------------------------------------------
__global__ void k_pre(const float* __restrict__ x, const float* __restrict__ W, int n) {
    int tid = blockIdx.x * blockDim.x + threadIdx.x;
    int nth = gridDim.x * blockDim.x;

    for (int i = tid; i < n; i += nth) g_cnt[i] = 0;

    for (int idx = tid; idx < IN_C * IN_C; idx += nth) {
        int o = idx >> 7, k = idx & (IN_C - 1);
        g_Wt[k * IN_C + o] = W[o * IN_C + k];
    }

    int n4 = n * (IN_C / 4);
    for (int idx = tid; idx < n4; idx += nth) {
        float4 v = ((const float4*)x)[idx];
        ((__half2*)g_xh)[idx * 2]     = __floats2half2_rn(v.x, v.y);
        ((__half2*)g_xh)[idx * 2 + 1] = __floats2half2_rn(v.z, v.w);
    }
}

// ---------------------------------------------------------------------------
// In-degree count: 4 edges per thread (batched loads, 4 REDs in flight)
// ---------------------------------------------------------------------------
__global__ void k_count(const void* __restrict__ ei_raw, int E) {
    int is64 = block_is64((const int*)ei_raw);
    int base = (blockIdx.x * blockDim.x + threadIdx.x) * 4;

    int c[4];
#pragma unroll
    for (int j = 0; j < 4; j++) {
        int e = base + j;
        if (e < E)
            c[j] = is64 ? (int)((const long long*)ei_raw)[(size_t)E + e]
                        : ((const int*)ei_raw)[E + e];
        else c[j] = -1;
    }
#pragma unroll
    for (int j = 0; j < 4; j++)
        if (c[j] >= 0) atomicAdd(&g_cnt[c[j]], 1);
}

// ---------------------------------------------------------------------------
// Warp-shuffle exclusive scan of g_cnt -> g_ptr, plus dinv and cursors.
// ---------------------------------------------------------------------------
__global__ void k_scan_dinv(int n) {
    __shared__ int warpsum[32];
    __shared__ int carry_s;
    int tid = threadIdx.x, lane = tid & 31, wid = tid >> 5;
    if (tid == 0) carry_s = 0;
    __syncthreads();

    for (int base = 0; base < n; base += 1024) {
        int i = base + tid;
        int v = (i < n) ? g_cnt[i] : 0;

        int incl = v;
#pragma unroll
        for (int off = 1; off < 32; off <<= 1) {
            int t = __shfl_up_sync(0xffffffff, incl, off);
            if (lane >= off) incl += t;
        }
        if (lane == 31) warpsum[wid] = incl;
        __syncthreads();
        if (wid == 0) {
            int s = warpsum[lane];
#pragma unroll
            for (int off = 1; off < 32; off <<= 1) {
                int t = __shfl_up_sync(0xffffffff, s, off);
                if (lane >= off) s += t;
            }
            warpsum[lane] = s;
        }
        __syncthreads();

        int warpbase = (wid > 0) ? warpsum[wid - 1] : 0;
        int excl = carry_s + warpbase + incl - v;
        if (i < n) {
            g_ptr[i]  = excl;
            g_cur[i]  = excl;
            g_dinv[i] = rsqrtf((float)(v + 1));    // +1 self loop
        }
        __syncthreads();
        if (tid == 0) carry_s += warpsum[31];
        __syncthreads();
    }
    if (tid == 0) g_ptr[n] = carry_s;
}

// ---------------------------------------------------------------------------
// CSR fill: 4 edges per thread (batched loads, 4 atomic+store pairs in flight)
// ---------------------------------------------------------------------------
__global__ void k_fill(const void* __restrict__ ei_raw, int E) {
    int is64 = block_is64((const int*)ei_raw);
    int base = (blockIdx.x * blockDim.x + threadIdx.x) * 4;

    int r[4], c[4];
#pragma unroll
    for (int j = 0; j < 4; j++) {
        int e = base + j;
        if (e < E) {
            if (is64) {
                const long long* p = (const long long*)ei_raw;
                r[j] = (int)p[e];
                c[j] = (int)p[(size_t)E + e];
            } else {
                const int* p = (const int*)ei_raw;
                r[j] = p[e];
                c[j] = p[E + e];
            }
        } else c[j] = -1;
    }
#pragma unroll
    for (int j = 0; j < 4; j++) {
        if (c[j] >= 0) {
            int pos = atomicAdd(&g_cur[c[j]], 1);
            g_erow[pos] = r[j];
        }
    }
}

// ---------------------------------------------------------------------------
// Fused aggregate + GEMM + bias. Block = 256 threads handles 32 nodes.
// Phase 1: warp w aggregates nodes rowbase+4w..4w+3 into shared xs
//          (fp16 gather, 8B loads, fp32 accumulate; self term fp32).
// Phase 2: out[32 x 128] = xs @ W^T + b from shared.
// ---------------------------------------------------------------------------
#define GM_ROWS 32
__global__ __launch_bounds__(256) void k_agg_gemm(const float* __restrict__ x,
                                                  const float* __restrict__ bvec,
                                                  float* __restrict__ out, int n) {
    __shared__ float xs[GM_ROWS][IN_C];

    int rowbase = blockIdx.x * GM_ROWS;
    int tid = threadIdx.x, warp = tid >> 5, lane = tid & 31;

    // ---- Phase 1: aggregate 4 nodes per warp ----
#pragma unroll
    for (int j = 0; j < 4; j++) {
        int node = rowbase + warp * 4 + j;
        if (node >= n) break;

        int s = g_ptr[node];
        int e = g_ptr[node + 1];

        float4 acc = make_float4(0.f, 0.f, 0.f, 0.f);
        const __half* xh_lane = g_xh + lane * 4;

        int i = s;
        for (; i + 4 <= e; i += 4) {
            int r0 = g_erow[i], r1 = g_erow[i + 1], r2 = g_erow[i + 2], r3 = g_erow[i + 3];
            float w0 = g_dinv[r0], w1 = g_dinv[r1], w2 = g_dinv[r2], w3 = g_dinv[r3];
            uint2 u0 = *(const uint2*)(xh_lane + (size_t)r0 * IN_C);
            uint2 u1 = *(const uint2*)(xh_lane + (size_t)r1 * IN_C);
            uint2 u2 = *(const uint2*)(xh_lane + (size_t)r2 * IN_C);
            uint2 u3 = *(const uint2*)(xh_lane + (size_t)r3 * IN_C);
            float2 f;
            f = __half22float2(*(__half2*)&u0.x); acc.x += w0 * f.x; acc.y += w0 * f.y;
            f = __half22float2(*(__half2*)&u0.y); acc.z += w0 * f.x; acc.w += w0 * f.y;
            f = __half22float2(*(__half2*)&u1.x); acc.x += w1 * f.x; acc.y += w1 * f.y;
            f = __half22float2(*(__half2*)&u1.y); acc.z += w1 * f.x; acc.w += w1 * f.y;
            f = __half22float2(*(__half2*)&u2.x); acc.x += w2 * f.x; acc.y += w2 * f.y;
            f = __half22float2(*(__half2*)&u2.y); acc.z += w2 * f.x; acc.w += w2 * f.y;
            f = __half22float2(*(__half2*)&u3.x); acc.x += w3 * f.x; acc.y += w3 * f.y;
            f = __half22float2(*(__half2*)&u3.y); acc.z += w3 * f.x; acc.w += w3 * f.y;
        }
        for (; i < e; i++) {
            int r = g_erow[i];
            float w = g_dinv[r];
            uint2 u = *(const uint2*)(xh_lane + (size_t)r * IN_C);
            float2 f;
            f = __half22float2(*(__half2*)&u.x); acc.x += w * f.x; acc.y += w * f.y;
            f = __half22float2(*(__half2*)&u.y); acc.z += w * f.x; acc.w += w * f.y;
        }

        float dc = g_dinv[node];
        float4 xv = *(const float4*)(x + (size_t)node * IN_C + lane * 4);
        float4 z;
        z.x = dc * (acc.x + dc * xv.x);
        z.y = dc * (acc.y + dc * xv.y);
        z.z = dc * (acc.z + dc * xv.z);
        z.w = dc * (acc.w + dc * xv.w);
        *(float4*)&xs[warp * 4 + j][lane * 4] = z;
    }
    __syncthreads();

    // ---- Phase 2: GEMM from shared ----
    int nrows = n - rowbase; if (nrows > GM_ROWS) nrows = GM_ROWS;
    int rg = warp >> 2;                       // row group (0..1), 16 rows each
    int o  = ((warp & 3) << 5) + lane;        // output column (0..127)

    float acc[16];
#pragma unroll
    for (int r = 0; r < 16; r++) acc[r] = 0.0f;

    const float* xbase = &xs[rg * 16][0];

#pragma unroll 4
    for (int k = 0; k < IN_C; k++) {
        float w = __ldg(&g_Wt[k * IN_C + o]);
#pragma unroll
        for (int r = 0; r < 16; r++)
            acc[r] += xbase[r * IN_C + k] * w;
    }

    float bo = __ldg(&bvec[o]);
    int rmax = nrows - rg * 16;
#pragma unroll
    for (int r = 0; r < 16; r++) {
        if (r < rmax)
            out[(size_t)(rowbase + rg * 16 + r) * IN_C + o] = acc[r] + bo;
    }
}

// ---------------------------------------------------------------------------
extern "C" void kernel_launch(void* const* d_in, const int* in_sizes, int n_in,
                              void* d_out, int out_size) {
    const float* x  = (const float*)d_in[0];       // [N, 128]
    const float* W  = (const float*)d_in[1];       // [128, 128]
    const float* b  = (const float*)d_in[2];       // [128]
    const void*  ei = d_in[3];                     // [2, E] int32 or int64

    int n = in_sizes[0] / IN_C;
    int E = in_sizes[3] / 2;
    float* out = (float*)d_out;

    int eb = (E / 4 + 255) / 256;                  // 4 edges per thread

    k_pre<<<80, 256>>>(x, W, n);
    k_count<<<eb, 256>>>(ei, E);
    k_scan_dinv<<<1, 1024>>>(n);
    k_fill<<<eb, 256>>>(ei, E);
    k_agg_gemm<<<(n + GM_ROWS - 1) / GM_ROWS, 256>>>(x, b, out, n);
}

// round 9
// speedup vs baseline: 1.3545x; 1.3545x over previous
#include <cuda_runtime.h>
#include <cuda_fp16.h>

#define IN_C 128
#define MAX_NODES 10000
#define MAX_EDGES 640000
#define NREP 8                      // sub-buckets per node
#define CAP 32                      // capacity per sub-bucket
#define SLOTS (NREP * CAP)          // 256 slots per node
#define MAXSPILL 4096

// Scratch (allocation-free rule: __device__ globals)
__device__ float  g_Wt[IN_C * IN_C];             // W transposed
__device__ float  g_z[MAX_NODES * IN_C];         // aggregated x (pre-GEMM)
__device__ __half g_xh[MAX_NODES * IN_C];        // fp16 copy of x for gather
__device__ int    g_cnt8[MAX_NODES * NREP];      // per-sub-bucket counts
__device__ float  g_dinv[MAX_NODES];             // 1/sqrt(deg+1)
__device__ int    g_erow[MAX_NODES * SLOTS];     // bucketed source-node list
__device__ int    g_nspill;
__device__ int    g_srow[MAXSPILL], g_scol[MAXSPILL];

// ---------------------------------------------------------------------------
// Per-block edge-index dtype detection: int64 data has all-zero odd 32-bit
// words (ids < 2^31); int32 data essentially never does (64 random ids all 0).
// ---------------------------------------------------------------------------
__device__ __forceinline__ int block_is64(const int* __restrict__ ei32) {
    int pred = 0;
    if (threadIdx.x < 64) pred = (ei32[2 * threadIdx.x + 1] != 0);
    return __syncthreads_or(pred) ? 0 : 1;
}

// ---------------------------------------------------------------------------
// Fused prologue: zero counters + transpose W + x -> fp16
// ---------------------------------------------------------------------------
__global__ void k_pre(const float* __restrict__ x, const float* __restrict__ W, int n) {
    int tid = blockIdx.x * blockDim.x + threadIdx.x;
    int nth = gridDim.x * blockDim.x;

    if (tid == 0) g_nspill = 0;
    for (int i = tid; i < n * NREP; i += nth) g_cnt8[i] = 0;

    for (int idx = tid; idx < IN_C * IN_C; idx += nth) {
        int o = idx >> 7, k = idx & (IN_C - 1);
        g_Wt[k * IN_C + o] = W[o * IN_C + k];
    }

    int n4 = n * (IN_C / 4);
    for (int idx = tid; idx < n4; idx += nth) {
        float4 v = ((const float4*)x)[idx];
        ((__half2*)g_xh)[idx * 2]     = __floats2half2_rn(v.x, v.y);
        ((__half2*)g_xh)[idx * 2 + 1] = __floats2half2_rn(v.z, v.w);
    }
}

// ---------------------------------------------------------------------------
// One-pass bucketed fill (count + place). Replica chosen by tid&7 spreads
// same-destination atomics over 8 addresses (contention 64 -> ~8).
// ---------------------------------------------------------------------------
__global__ void k_fill(const void* __restrict__ ei_raw, int E) {
    int is64 = block_is64((const int*)ei_raw);
    int e = blockIdx.x * blockDim.x + threadIdx.x;
    if (e >= E) return;

    int row, col;
    if (is64) {
        const long long* p = (const long long*)ei_raw;
        row = (int)p[e];
        col = (int)p[(size_t)E + e];
    } else {
        const int* p = (const int*)ei_raw;
        row = p[e];
        col = p[E + e];
    }

    int r = threadIdx.x & (NREP - 1);
    int pos = atomicAdd(&g_cnt8[col * NREP + r], 1);
    if (pos < CAP) {
        g_erow[col * SLOTS + r * CAP + pos] = row;
    } else {
        int sp = atomicAdd(&g_nspill, 1);
        if (sp < MAXSPILL) { g_srow[sp] = row; g_scol[sp] = col; }
    }
}

// ---------------------------------------------------------------------------
// deg = sum of 8 sub-bucket counts (raw, includes spill); dinv = rsqrt(deg+1)
// ---------------------------------------------------------------------------
__global__ void k_dinv(int n) {
    int i = blockIdx.x * blockDim.x + threadIdx.x;
    if (i >= n) return;
    const int4* p = (const int4*)(g_cnt8 + i * NREP);
    int4 a = p[0], b = p[1];
    int deg = a.x + a.y + a.z + a.w + b.x + b.y + b.z + b.w;
    g_dinv[i] = rsqrtf((float)(deg + 1));   // +1 self loop
}

// ---------------------------------------------------------------------------
// Aggregate (atomic-free): warp per node, lane owns 4 channels.
// Iterates the node's 8 sub-buckets; fp16 gather (8B), fp32 accumulate.
// z[c] = dinv[c] * ( sum_{e->c} dinv[r]*xh[r] + dinv[c]*x[c] )
// ---------------------------------------------------------------------------
__global__ __launch_bounds__(256) void k_aggregate(const float* __restrict__ x, int n) {
    int node = (blockIdx.x * blockDim.x + threadIdx.x) >> 5;
    if (node >= n) return;
    int lane = threadIdx.x & 31;

    // lane r<8 holds count of sub-bucket r (clamped to CAP)
    int cnt_l = 0;
    if (lane < NREP) {
        cnt_l = g_cnt8[node * NREP + lane];
        if (cnt_l > CAP) cnt_l = CAP;
    }

    float4 acc = make_float4(0.f, 0.f, 0.f, 0.f);
    const __half* xh_lane = g_xh + lane * 4;

#pragma unroll
    for (int r = 0; r < NREP; r++) {
        int m = __shfl_sync(0xffffffff, cnt_l, r);
        const int* bucket = g_erow + (size_t)node * SLOTS + r * CAP;
        int i = 0;
        for (; i + 4 <= m; i += 4) {
            int r0 = bucket[i], r1 = bucket[i + 1], r2 = bucket[i + 2], r3 = bucket[i + 3];
            float w0 = g_dinv[r0], w1 = g_dinv[r1], w2 = g_dinv[r2], w3 = g_dinv[r3];
            uint2 u0 = *(const uint2*)(xh_lane + (size_t)r0 * IN_C);
            uint2 u1 = *(const uint2*)(xh_lane + (size_t)r1 * IN_C);
            uint2 u2 = *(const uint2*)(xh_lane + (size_t)r2 * IN_C);
            uint2 u3 = *(const uint2*)(xh_lane + (size_t)r3 * IN_C);
            float2 f;
            f = __half22float2(*(__half2*)&u0.x); acc.x += w0 * f.x; acc.y += w0 * f.y;
            f = __half22float2(*(__half2*)&u0.y); acc.z += w0 * f.x; acc.w += w0 * f.y;
            f = __half22float2(*(__half2*)&u1.x); acc.x += w1 * f.x; acc.y += w1 * f.y;
            f = __half22float2(*(__half2*)&u1.y); acc.z += w1 * f.x; acc.w += w1 * f.y;
            f = __half22float2(*(__half2*)&u2.x); acc.x += w2 * f.x; acc.y += w2 * f.y;
            f = __half22float2(*(__half2*)&u2.y); acc.z += w2 * f.x; acc.w += w2 * f.y;
            f = __half22float2(*(__half2*)&u3.x); acc.x += w3 * f.x; acc.y += w3 * f.y;
            f = __half22float2(*(__half2*)&u3.y); acc.z += w3 * f.x; acc.w += w3 * f.y;
        }
        for (; i < m; i++) {
            int rr = bucket[i];
            float w = g_dinv[rr];
            uint2 u = *(const uint2*)(xh_lane + (size_t)rr * IN_C);
            float2 f;
            f = __half22float2(*(__half2*)&u.x); acc.x += w * f.x; acc.y += w * f.y;
            f = __half22float2(*(__half2*)&u.y); acc.z += w * f.x; acc.w += w * f.y;
        }
    }

    float dc = g_dinv[node];
    float4 xv = *(const float4*)(x + (size_t)node * IN_C + lane * 4);  // self term fp32
    float4 z;
    z.x = dc * (acc.x + dc * xv.x);
    z.y = dc * (acc.y + dc * xv.y);
    z.z = dc * (acc.z + dc * xv.z);
    z.w = dc * (acc.w + dc * xv.w);
    *(float4*)(g_z + (size_t)node * IN_C + lane * 4) = z;
}

// ---------------------------------------------------------------------------
// Spill fixup (in practice 0 entries): add dropped messages into z.
// ---------------------------------------------------------------------------
__global__ void k_spill(const float* __restrict__ x) {
    int ns = g_nspill;
    if (ns > MAXSPILL) ns = MAXSPILL;
    for (int idx = threadIdx.x; idx < ns * IN_C; idx += blockDim.x) {
        int e = idx >> 7, ch = idx & (IN_C - 1);
        int row = g_srow[e], col = g_scol[e];
        float w = g_dinv[row] * g_dinv[col];
        atomicAdd(&g_z[(size_t)col * IN_C + ch], w * x[(size_t)row * IN_C + ch]);
    }
}

// ---------------------------------------------------------------------------
// GEMM + bias: out = z @ W^T + b. Block = 256 threads, 32 rows x 128 cols.
// ---------------------------------------------------------------------------
#define GM_ROWS 32
__global__ __launch_bounds__(256) void k_gemm_bias(const float* __restrict__ bvec,
                                                    float* __restrict__ out, int n) {
    __shared__ float xs[GM_ROWS][IN_C];

    int rowbase = blockIdx.x * GM_ROWS;
    int tid = threadIdx.x;
    int nrows = n - rowbase; if (nrows > GM_ROWS) nrows = GM_ROWS;

    const float4* xg = (const float4*)(g_z + (size_t)rowbase * IN_C);
    float4* xs4 = (float4*)&xs[0][0];
#pragma unroll
    for (int i = 0; i < 4; i++) {
        int idx = tid + i * 256;
        if ((idx >> 5) < nrows) xs4[idx] = xg[idx];
    }
    __syncthreads();

    int warp = tid >> 5, lane = tid & 31;
    int rg = warp >> 2;                       // row group (0..1), 16 rows each
    int o  = ((warp & 3) << 5) + lane;        // output column (0..127)

    float acc[16];
#pragma unroll
    for (int r = 0; r < 16; r++) acc[r] = 0.0f;

    const float* xbase = &xs[rg * 16][0];

#pragma unroll 4
    for (int k = 0; k < IN_C; k++) {
        float w = __ldg(&g_Wt[k * IN_C + o]);
#pragma unroll
        for (int r = 0; r < 16; r++)
            acc[r] += xbase[r * IN_C + k] * w;
    }

    float bo = __ldg(&bvec[o]);
    int rmax = nrows - rg * 16;
#pragma unroll
    for (int r = 0; r < 16; r++) {
        if (r < rmax)
            out[(size_t)(rowbase + rg * 16 + r) * IN_C + o] = acc[r] + bo;
    }
}

// ---------------------------------------------------------------------------
extern "C" void kernel_launch(void* const* d_in, const int* in_sizes, int n_in,
                              void* d_out, int out_size) {
    const float* x  = (const float*)d_in[0];       // [N, 128]
    const float* W  = (const float*)d_in[1];       // [128, 128]
    const float* b  = (const float*)d_in[2];       // [128]
    const void*  ei = d_in[3];                     // [2, E] int32 or int64

    int n = in_sizes[0] / IN_C;
    int E = in_sizes[3] / 2;
    float* out = (float*)d_out;

    k_pre<<<80, 256>>>(x, W, n);
    k_fill<<<(E + 255) / 256, 256>>>(ei, E);
    k_dinv<<<(n + 255) / 256, 256>>>(n);
    k_aggregate<<<(n + 7) / 8, 256>>>(x, n);
    k_spill<<<1, 256>>>(x);
    k_gemm_bias<<<(n + GM_ROWS - 1) / GM_ROWS, 256>>>(b, out, n);
}

// round 12
// speedup vs baseline: 1.4828x; 1.0947x over previous
#include <cuda_runtime.h>
#include <cuda_fp16.h>

#define IN_C 128
#define MAX_NODES 10000
#define MAX_EDGES 640000
#define NREP 8                      // sub-buckets per node
#define CAP 32                      // capacity per sub-bucket
#define SLOTS (NREP * CAP)          // 256 slots per node
#define MAXSPILL 4096

// Scratch (allocation-free rule: __device__ globals). All zero-initialized at
// module load; every kernel_launch leaves counters zeroed for the next replay.
__device__ float  g_Wt[IN_C * IN_C];             // W transposed
__device__ float  g_z[MAX_NODES * IN_C];         // aggregated x (pre-GEMM)
__device__ __half g_xh[MAX_NODES * IN_C];        // fp16 dinv[r]*x[r] gather table
__device__ int    g_cnt8[MAX_NODES * NREP];      // per-sub-bucket counts
__device__ float  g_dinv[MAX_NODES];             // 1/sqrt(deg+1)
__device__ int    g_erow[MAX_NODES * SLOTS];     // bucketed source-node list
__device__ int    g_nspill;
__device__ int    g_srow[MAXSPILL], g_scol[MAXSPILL];

// ---------------------------------------------------------------------------
// Per-block edge-index dtype detection: int64 data has all-zero odd 32-bit
// words (ids < 2^31); int32 data essentially never does (64 random ids all 0).
// ---------------------------------------------------------------------------
__device__ __forceinline__ int block_is64(const int* __restrict__ ei32) {
    int pred = 0;
    if (threadIdx.x < 64) pred = (ei32[2 * threadIdx.x + 1] != 0);
    return __syncthreads_or(pred) ? 0 : 1;
}

// ---------------------------------------------------------------------------
// One-pass bucketed fill (count + place). Replica chosen by tid&7 spreads
// same-destination atomics over 8 addresses. cnt8 was zeroed by the previous
// launch's k_aggregate (or module load on the first call).
// ---------------------------------------------------------------------------
__global__ void k_fill(const void* __restrict__ ei_raw, int E) {
    int is64 = block_is64((const int*)ei_raw);
    int e = blockIdx.x * blockDim.x + threadIdx.x;
    if (e >= E) return;

    int row, col;
    if (is64) {
        const long long* p = (const long long*)ei_raw;
        row = (int)p[e];
        col = (int)p[(size_t)E + e];
    } else {
        const int* p = (const int*)ei_raw;
        row = p[e];
        col = p[E + e];
    }

    int r = threadIdx.x & (NREP - 1);
    int pos = atomicAdd(&g_cnt8[col * NREP + r], 1);
    if (pos < CAP) {
        g_erow[col * SLOTS + r * CAP + pos] = row;
    } else {
        int sp = atomicAdd(&g_nspill, 1);
        if (sp < MAXSPILL) { g_srow[sp] = row; g_scol[sp] = col; }
    }
}

// ---------------------------------------------------------------------------
// dinv + pre-scaled fp16 table + W transpose.
// Block handles 64 nodes: phase A computes dinv (threads 0..63), phase B
// scales the 64 rows into g_xh (fp16), phase C (first 64 blocks) transposes W.
// ---------------------------------------------------------------------------
__global__ __launch_bounds__(256) void k_dinv_scale(const float* __restrict__ x,
                                                    const float* __restrict__ W, int n) {
    __shared__ float sdinv[64];
    int base = blockIdx.x * 64;
    int tid = threadIdx.x;

    if (tid < 64) {
        int node = base + tid;
        float d = 0.0f;
        if (node < n) {
            const int4* p = (const int4*)(g_cnt8 + node * NREP);
            int4 a = p[0], b = p[1];
            int deg = a.x + a.y + a.z + a.w + b.x + b.y + b.z + b.w;
            d = rsqrtf((float)(deg + 1));     // +1 self loop
            g_dinv[node] = d;
        }
        sdinv[tid] = d;
    }
    __syncthreads();

    // 64 rows x 32 float4 = 2048 units; 256 threads x 8 iters
#pragma unroll
    for (int j = 0; j < 8; j++) {
        int idx = tid + j * 256;
        int rloc = idx >> 5;
        int node = base + rloc;
        if (node < n) {
            int c4 = idx & 31;
            float d = sdinv[rloc];
            float4 v = *(const float4*)(x + (size_t)node * IN_C + c4 * 4);
            __half2* dst = (__half2*)(g_xh + (size_t)node * IN_C + c4 * 4);
            dst[0] = __floats2half2_rn(d * v.x, d * v.y);
            dst[1] = __floats2half2_rn(d * v.z, d * v.w);
        }
    }

    // W transpose: 16384 elements over first 64 blocks
    int widx = blockIdx.x * 256 + tid;
    if (widx < IN_C * IN_C) {
        int o = widx >> 7, k = widx & (IN_C - 1);
        g_Wt[k * IN_C + o] = W[o * IN_C + k];
    }
}

// ---------------------------------------------------------------------------
// Aggregate (atomic-free): warp per node, lane owns 4 channels (8B fp16).
// Table is pre-scaled, so the inner loop is pure gather+add (fp32 accum).
// Also handles spill entries (≈0) and zeroes its node's counters for the
// next replay.
// z[c] = dinv[c] * ( sum_{e->c} xh[r] + dinv[c]*x[c] )
// ---------------------------------------------------------------------------
__global__ __launch_bounds__(256) void k_aggregate(const float* __restrict__ x, int n) {
    int node = (blockIdx.x * blockDim.x + threadIdx.x) >> 5;
    if (node >= n) return;
    int lane = threadIdx.x & 31;

    int cnt_l = 0;
    if (lane < NREP) {
        cnt_l = g_cnt8[node * NREP + lane];
        if (cnt_l > CAP) cnt_l = CAP;
    }

    float4 acc = make_float4(0.f, 0.f, 0.f, 0.f);
    const __half* xh_lane = g_xh + lane * 4;

#pragma unroll
    for (int r = 0; r < NREP; r++) {
        int m = __shfl_sync(0xffffffff, cnt_l, r);
        const int* bucket = g_erow + (size_t)node * SLOTS + r * CAP;
        int i = 0;
        for (; i + 8 <= m; i += 8) {
            int rr[8];
#pragma unroll
            for (int j = 0; j < 8; j++) rr[j] = bucket[i + j];
            uint2 u[8];
#pragma unroll
            for (int j = 0; j < 8; j++) u[j] = *(const uint2*)(xh_lane + (size_t)rr[j] * IN_C);
#pragma unroll
            for (int j = 0; j < 8; j++) {
                float2 f0 = __half22float2(*(__half2*)&u[j].x);
                float2 f1 = __half22float2(*(__half2*)&u[j].y);
                acc.x += f0.x; acc.y += f0.y; acc.z += f1.x; acc.w += f1.y;
            }
        }
        for (; i + 4 <= m; i += 4) {
            int r0 = bucket[i], r1 = bucket[i + 1], r2 = bucket[i + 2], r3 = bucket[i + 3];
            uint2 u0 = *(const uint2*)(xh_lane + (size_t)r0 * IN_C);
            uint2 u1 = *(const uint2*)(xh_lane + (size_t)r1 * IN_C);
            uint2 u2 = *(const uint2*)(xh_lane + (size_t)r2 * IN_C);
            uint2 u3 = *(const uint2*)(xh_lane + (size_t)r3 * IN_C);
            float2 f;
            f = __half22float2(*(__half2*)&u0.x); acc.x += f.x; acc.y += f.y;
            f = __half22float2(*(__half2*)&u0.y); acc.z += f.x; acc.w += f.y;
            f = __half22float2(*(__half2*)&u1.x); acc.x += f.x; acc.y += f.y;
            f = __half22float2(*(__half2*)&u1.y); acc.z += f.x; acc.w += f.y;
            f = __half22float2(*(__half2*)&u2.x); acc.x += f.x; acc.y += f.y;
            f = __half22float2(*(__half2*)&u2.y); acc.z += f.x; acc.w += f.y;
            f = __half22float2(*(__half2*)&u3.x); acc.x += f.x; acc.y += f.y;
            f = __half22float2(*(__half2*)&u3.y); acc.z += f.x; acc.w += f.y;
        }
        for (; i < m; i++) {
            int rr = bucket[i];
            uint2 u = *(const uint2*)(xh_lane + (size_t)rr * IN_C);
            float2 f;
            f = __half22float2(*(__half2*)&u.x); acc.x += f.x; acc.y += f.y;
            f = __half22float2(*(__half2*)&u.y); acc.z += f.x; acc.w += f.y;
        }
    }

    // Spill entries (expected 0): fp32 fixup
    int ns = g_nspill;
    if (ns > 0) {
        if (ns > MAXSPILL) ns = MAXSPILL;
        for (int j = 0; j < ns; j++) {
            if (g_scol[j] == node) {
                int rr = g_srow[j];
                float w = g_dinv[rr];
                float4 v = *(const float4*)(x + (size_t)rr * IN_C + lane * 4);
                acc.x += w * v.x; acc.y += w * v.y; acc.z += w * v.z; acc.w += w * v.w;
            }
        }
    }

    float dc = g_dinv[node];
    float4 xv = *(const float4*)(x + (size_t)node * IN_C + lane * 4);  // self term fp32
    float4 z;
    z.x = dc * (acc.x + dc * xv.x);
    z.y = dc * (acc.y + dc * xv.y);
    z.z = dc * (acc.z + dc * xv.z);
    z.w = dc * (acc.w + dc * xv.w);
    *(float4*)(g_z + (size_t)node * IN_C + lane * 4) = z;

    // Self-clean counters for the next replay (values already consumed)
    if (lane < NREP) g_cnt8[node * NREP + lane] = 0;
}

// ---------------------------------------------------------------------------
// GEMM + bias: out = z @ W^T + b. Block = 256 threads, 32 rows x 128 cols.
// Also resets the spill counter for the next replay.
// ---------------------------------------------------------------------------
#define GM_ROWS 32
__global__ __launch_bounds__(256) void k_gemm_bias(const float* __restrict__ bvec,
                                                    float* __restrict__ out, int n) {
    if (blockIdx.x == 0 && threadIdx.x == 0) g_nspill = 0;

    __shared__ float xs[GM_ROWS][IN_C];

    int rowbase = blockIdx.x * GM_ROWS;
    int tid = threadIdx.x;
    int nrows = n - rowbase; if (nrows > GM_ROWS) nrows = GM_ROWS;

    const float4* xg = (const float4*)(g_z + (size_t)rowbase * IN_C);
    float4* xs4 = (float4*)&xs[0][0];
#pragma unroll
    for (int i = 0; i < 4; i++) {
        int idx = tid + i * 256;
        if ((idx >> 5) < nrows) xs4[idx] = xg[idx];
    }
    __syncthreads();

    int warp = tid >> 5, lane = tid & 31;
    int rg = warp >> 2;                       // row group (0..1), 16 rows each
    int o  = ((warp & 3) << 5) + lane;        // output column (0..127)

    float acc[16];
#pragma unroll
    for (int r = 0; r < 16; r++) acc[r] = 0.0f;

    const float* xbase = &xs[rg * 16][0];

#pragma unroll 4
    for (int k = 0; k < IN_C; k++) {
        float w = __ldg(&g_Wt[k * IN_C + o]);
#pragma unroll
        for (int r = 0; r < 16; r++)
            acc[r] += xbase[r * IN_C + k] * w;
    }

    float bo = __ldg(&bvec[o]);
    int rmax = nrows - rg * 16;
#pragma unroll
    for (int r = 0; r < 16; r++) {
        if (r < rmax)
            out[(size_t)(rowbase + rg * 16 + r) * IN_C + o] = acc[r] + bo;
    }
}

// ---------------------------------------------------------------------------
extern "C" void kernel_launch(void* const* d_in, const int* in_sizes, int n_in,
                              void* d_out, int out_size) {
    const float* x  = (const float*)d_in[0];       // [N, 128]
    const float* W  = (const float*)d_in[1];       // [128, 128]
    const float* b  = (const float*)d_in[2];       // [128]
    const void*  ei = d_in[3];                     // [2, E] int32 or int64

    int n = in_sizes[0] / IN_C;
    int E = in_sizes[3] / 2;
    float* out = (float*)d_out;

    k_fill<<<(E + 255) / 256, 256>>>(ei, E);
    k_dinv_scale<<<(n + 63) / 64, 256>>>(x, W, n);
    k_aggregate<<<(n + 7) / 8, 256>>>(x, n);
    k_gemm_bias<<<(n + GM_ROWS - 1) / GM_ROWS, 256>>>(b, out, n);
}

// round 13
// speedup vs baseline: 1.6519x; 1.1141x over previous
#include <cuda_runtime.h>
#include <cuda_fp16.h>

#define IN_C 128
#define MAX_NODES 10000
#define MAX_EDGES 640000
#define NREP 8                      // sub-buckets per node
#define CAP 32                      // capacity per sub-bucket
#define SLOTS (NREP * CAP)          // 256 slots per node
#define MAXSPILL 4096

// Scratch (allocation-free rule: __device__ globals). All zero-initialized at
// module load; every kernel_launch leaves counters zeroed for the next replay.
__device__ float4 g_Wp[(IN_C / 4) * IN_C];       // packed W: g_Wp[k4*128+o] = W[o][4k4..4k4+3]
__device__ float  g_z[MAX_NODES * IN_C];         // aggregated x (pre-GEMM)
__device__ __half g_xh[MAX_NODES * IN_C];        // fp16 dinv[r]*x[r] gather table
__device__ int    g_cnt8[MAX_NODES * NREP];      // per-sub-bucket counts
__device__ float  g_dinv[MAX_NODES];             // 1/sqrt(deg+1)
__device__ int    g_erow[MAX_NODES * SLOTS];     // bucketed source-node list
__device__ int    g_nspill;
__device__ int    g_srow[MAXSPILL], g_scol[MAXSPILL];

// ---------------------------------------------------------------------------
// Per-block edge-index dtype detection: int64 data has all-zero odd 32-bit
// words (ids < 2^31); int32 data essentially never does (64 random ids all 0).
// ---------------------------------------------------------------------------
__device__ __forceinline__ int block_is64(const int* __restrict__ ei32) {
    int pred = 0;
    if (threadIdx.x < 64) pred = (ei32[2 * threadIdx.x + 1] != 0);
    return __syncthreads_or(pred) ? 0 : 1;
}

// ---------------------------------------------------------------------------
// One-pass bucketed fill (count + place). Replica chosen by tid&7 spreads
// same-destination atomics over 8 addresses. cnt8 was zeroed by the previous
// launch's k_aggregate (or module load on the first call).
// ---------------------------------------------------------------------------
__global__ void k_fill(const void* __restrict__ ei_raw, int E) {
    int is64 = block_is64((const int*)ei_raw);
    int e = blockIdx.x * blockDim.x + threadIdx.x;
    if (e >= E) return;

    int row, col;
    if (is64) {
        const long long* p = (const long long*)ei_raw;
        row = (int)p[e];
        col = (int)p[(size_t)E + e];
    } else {
        const int* p = (const int*)ei_raw;
        row = p[e];
        col = p[E + e];
    }

    int r = threadIdx.x & (NREP - 1);
    int pos = atomicAdd(&g_cnt8[col * NREP + r], 1);
    if (pos < CAP) {
        g_erow[col * SLOTS + r * CAP + pos] = row;
    } else {
        int sp = atomicAdd(&g_nspill, 1);
        if (sp < MAXSPILL) { g_srow[sp] = row; g_scol[sp] = col; }
    }
}

// ---------------------------------------------------------------------------
// dinv + pre-scaled fp16 table + W pack.
// Block handles 64 nodes: phase A computes dinv (threads 0..63), phase B
// scales the 64 rows into g_xh (fp16), phase C (first 16 blocks) packs W into
// g_Wp[k4*128+o] = float4 of W[o][4k4..4k4+3] (coalesced GEMM weight loads).
// ---------------------------------------------------------------------------
__global__ __launch_bounds__(256) void k_dinv_scale(const float* __restrict__ x,
                                                    const float* __restrict__ W, int n) {
    __shared__ float sdinv[64];
    int base = blockIdx.x * 64;
    int tid = threadIdx.x;

    if (tid < 64) {
        int node = base + tid;
        float d = 0.0f;
        if (node < n) {
            const int4* p = (const int4*)(g_cnt8 + node * NREP);
            int4 a = p[0], b = p[1];
            int deg = a.x + a.y + a.z + a.w + b.x + b.y + b.z + b.w;
            d = rsqrtf((float)(deg + 1));     // +1 self loop
            g_dinv[node] = d;
        }
        sdinv[tid] = d;
    }
    __syncthreads();

    // 64 rows x 32 float4 = 2048 units; 256 threads x 8 iters
#pragma unroll
    for (int j = 0; j < 8; j++) {
        int idx = tid + j * 256;
        int rloc = idx >> 5;
        int node = base + rloc;
        if (node < n) {
            int c4 = idx & 31;
            float d = sdinv[rloc];
            float4 v = *(const float4*)(x + (size_t)node * IN_C + c4 * 4);
            __half2* dst = (__half2*)(g_xh + (size_t)node * IN_C + c4 * 4);
            dst[0] = __floats2half2_rn(d * v.x, d * v.y);
            dst[1] = __floats2half2_rn(d * v.z, d * v.w);
        }
    }

    // W pack: 4096 float4 entries over first 16 blocks
    int widx = blockIdx.x * 256 + tid;
    if (widx < (IN_C / 4) * IN_C) {
        int k4 = widx >> 7, o = widx & (IN_C - 1);
        const float* wrow = W + o * IN_C + k4 * 4;
        g_Wp[widx] = make_float4(wrow[0], wrow[1], wrow[2], wrow[3]);
    }
}

// ---------------------------------------------------------------------------
// Aggregate (atomic-free): warp per node, lane owns 4 channels (8B fp16).
// Table is pre-scaled, so the inner loop is pure gather+add (fp32 accum).
// Also handles spill entries (≈0) and zeroes its node's counters for the
// next replay.
// z[c] = dinv[c] * ( sum_{e->c} xh[r] + dinv[c]*x[c] )
// ---------------------------------------------------------------------------
__global__ __launch_bounds__(256) void k_aggregate(const float* __restrict__ x, int n) {
    int node = (blockIdx.x * blockDim.x + threadIdx.x) >> 5;
    if (node >= n) return;
    int lane = threadIdx.x & 31;

    int cnt_l = 0;
    if (lane < NREP) {
        cnt_l = g_cnt8[node * NREP + lane];
        if (cnt_l > CAP) cnt_l = CAP;
    }

    float4 acc = make_float4(0.f, 0.f, 0.f, 0.f);
    const __half* xh_lane = g_xh + lane * 4;

#pragma unroll
    for (int r = 0; r < NREP; r++) {
        int m = __shfl_sync(0xffffffff, cnt_l, r);
        const int* bucket = g_erow + (size_t)node * SLOTS + r * CAP;
        int i = 0;
        for (; i + 8 <= m; i += 8) {
            int rr[8];
#pragma unroll
            for (int j = 0; j < 8; j++) rr[j] = bucket[i + j];
            uint2 u[8];
#pragma unroll
            for (int j = 0; j < 8; j++) u[j] = *(const uint2*)(xh_lane + (size_t)rr[j] * IN_C);
#pragma unroll
            for (int j = 0; j < 8; j++) {
                float2 f0 = __half22float2(*(__half2*)&u[j].x);
                float2 f1 = __half22float2(*(__half2*)&u[j].y);
                acc.x += f0.x; acc.y += f0.y; acc.z += f1.x; acc.w += f1.y;
            }
        }
        for (; i + 4 <= m; i += 4) {
            int r0 = bucket[i], r1 = bucket[i + 1], r2 = bucket[i + 2], r3 = bucket[i + 3];
            uint2 u0 = *(const uint2*)(xh_lane + (size_t)r0 * IN_C);
            uint2 u1 = *(const uint2*)(xh_lane + (size_t)r1 * IN_C);
            uint2 u2 = *(const uint2*)(xh_lane + (size_t)r2 * IN_C);
            uint2 u3 = *(const uint2*)(xh_lane + (size_t)r3 * IN_C);
            float2 f;
            f = __half22float2(*(__half2*)&u0.x); acc.x += f.x; acc.y += f.y;
            f = __half22float2(*(__half2*)&u0.y); acc.z += f.x; acc.w += f.y;
            f = __half22float2(*(__half2*)&u1.x); acc.x += f.x; acc.y += f.y;
            f = __half22float2(*(__half2*)&u1.y); acc.z += f.x; acc.w += f.y;
            f = __half22float2(*(__half2*)&u2.x); acc.x += f.x; acc.y += f.y;
            f = __half22float2(*(__half2*)&u2.y); acc.z += f.x; acc.w += f.y;
            f = __half22float2(*(__half2*)&u3.x); acc.x += f.x; acc.y += f.y;
            f = __half22float2(*(__half2*)&u3.y); acc.z += f.x; acc.w += f.y;
        }
        for (; i < m; i++) {
            int rr = bucket[i];
            uint2 u = *(const uint2*)(xh_lane + (size_t)rr * IN_C);
            float2 f;
            f = __half22float2(*(__half2*)&u.x); acc.x += f.x; acc.y += f.y;
            f = __half22float2(*(__half2*)&u.y); acc.z += f.x; acc.w += f.y;
        }
    }

    // Spill entries (expected 0): fp32 fixup
    int ns = g_nspill;
    if (ns > 0) {
        if (ns > MAXSPILL) ns = MAXSPILL;
        for (int j = 0; j < ns; j++) {
            if (g_scol[j] == node) {
                int rr = g_srow[j];
                float w = g_dinv[rr];
                float4 v = *(const float4*)(x + (size_t)rr * IN_C + lane * 4);
                acc.x += w * v.x; acc.y += w * v.y; acc.z += w * v.z; acc.w += w * v.w;
            }
        }
    }

    float dc = g_dinv[node];
    float4 xv = *(const float4*)(x + (size_t)node * IN_C + lane * 4);  // self term fp32
    float4 z;
    z.x = dc * (acc.x + dc * xv.x);
    z.y = dc * (acc.y + dc * xv.y);
    z.z = dc * (acc.z + dc * xv.z);
    z.w = dc * (acc.w + dc * xv.w);
    *(float4*)(g_z + (size_t)node * IN_C + lane * 4) = z;

    // Self-clean counters for the next replay (values already consumed)
    if (lane < NREP) g_cnt8[node * NREP + lane] = 0;
}

// ---------------------------------------------------------------------------
// GEMM + bias: out = z @ W^T + b. Block = 256 threads, 32 rows x 128 cols.
// k vectorized: per 4-k chunk, 1 coalesced LDG.128 of packed W + 16 broadcast
// LDS.128 + 64 FFMA (FFMA-bound). Also resets the spill counter.
// ---------------------------------------------------------------------------
#define GM_ROWS 32
__global__ __launch_bounds__(256) void k_gemm_bias(const float* __restrict__ bvec,
                                                    float* __restrict__ out, int n) {
    if (blockIdx.x == 0 && threadIdx.x == 0) g_nspill = 0;

    __shared__ float xs[GM_ROWS][IN_C];

    int rowbase = blockIdx.x * GM_ROWS;
    int tid = threadIdx.x;
    int nrows = n - rowbase; if (nrows > GM_ROWS) nrows = GM_ROWS;

    const float4* xg = (const float4*)(g_z + (size_t)rowbase * IN_C);
    float4* xs4 = (float4*)&xs[0][0];
#pragma unroll
    for (int i = 0; i < 4; i++) {
        int idx = tid + i * 256;
        if ((idx >> 5) < nrows) xs4[idx] = xg[idx];
    }
    __syncthreads();

    int warp = tid >> 5, lane = tid & 31;
    int rg = warp >> 2;                       // row group (0..1), 16 rows each
    int o  = ((warp & 3) << 5) + lane;        // output column (0..127)

    float acc[16];
#pragma unroll
    for (int r = 0; r < 16; r++) acc[r] = 0.0f;

    const float* xbase = &xs[rg * 16][0];

#pragma unroll 4
    for (int k4 = 0; k4 < IN_C / 4; k4++) {
        float4 w4 = __ldg(&g_Wp[k4 * IN_C + o]);
#pragma unroll
        for (int r = 0; r < 16; r++) {
            float4 xv = *(const float4*)(xbase + r * IN_C + k4 * 4);
            float a = acc[r];
            a = fmaf(xv.x, w4.x, a);
            a = fmaf(xv.y, w4.y, a);
            a = fmaf(xv.z, w4.z, a);
            a = fmaf(xv.w, w4.w, a);
            acc[r] = a;
        }
    }

    float bo = __ldg(&bvec[o]);
    int rmax = nrows - rg * 16;
#pragma unroll
    for (int r = 0; r < 16; r++) {
        if (r < rmax)
            out[(size_t)(rowbase + rg * 16 + r) * IN_C + o] = acc[r] + bo;
    }
}

// ---------------------------------------------------------------------------
extern "C" void kernel_launch(void* const* d_in, const int* in_sizes, int n_in,
                              void* d_out, int out_size) {
    const float* x  = (const float*)d_in[0];       // [N, 128]
    const float* W  = (const float*)d_in[1];       // [128, 128]
    const float* b  = (const float*)d_in[2];       // [128]
    const void*  ei = d_in[3];                     // [2, E] int32 or int64

    int n = in_sizes[0] / IN_C;
    int E = in_sizes[3] / 2;
    float* out = (float*)d_out;

    k_fill<<<(E + 255) / 256, 256>>>(ei, E);
    k_dinv_scale<<<(n + 63) / 64, 256>>>(x, W, n);
    k_aggregate<<<(n + 7) / 8, 256>>>(x, n);
    k_gemm_bias<<<(n + GM_ROWS - 1) / GM_ROWS, 256>>>(b, out, n);
}